// round 4
// baseline (speedup 1.0000x reference)
#include <cuda_runtime.h>
#include <math.h>
#include <stdint.h>

#define D 128
#define MAXN 50000
#define MAXE 800000
#define NBS ((MAXN + 1023) / 1024)

// ---------------- scratch ----------------
__device__ float g_H [MAXN * D];
__device__ float g_A1[MAXN * D];
__device__ float g_A2[MAXN * D];
__device__ float g_HM[MAXN * D];
__device__ int   g_degF[MAXN];
__device__ int   g_degR[MAXN];
__device__ int   g_offF[MAXN];
__device__ int   g_offR[MAXN];
__device__ int   g_curF[MAXN];
__device__ int   g_curR[MAXN];
__device__ float g_dF[MAXN];
__device__ float g_dR[MAXN];
__device__ int2  g_csrF[MAXE];
__device__ int2  g_csrR[MAXE];
__device__ float g_W1T[D * D];
__device__ float g_W2T[D * D];
__device__ int   g_bsF[NBS + 1];
__device__ int   g_bsR[NBS + 1];

__device__ __forceinline__ float tf32_rna(float a) {
    uint32_t u;
    asm("cvt.rna.tf32.f32 %0, %1;" : "=r"(u) : "f"(a));
    return __uint_as_float(u);
}
__device__ __forceinline__ void mma8(float* d, uint32_t a0, uint32_t a1, uint32_t a2,
                                     uint32_t a3, uint32_t b0, uint32_t b1) {
    asm volatile("mma.sync.aligned.m16n8k8.row.col.f32.tf32.tf32.f32 "
                 "{%0,%1,%2,%3}, {%4,%5,%6,%7}, {%8,%9}, {%0,%1,%2,%3};"
                 : "+f"(d[0]), "+f"(d[1]), "+f"(d[2]), "+f"(d[3])
                 : "r"(a0), "r"(a1), "r"(a2), "r"(a3), "r"(b0), "r"(b1));
}

// ---------------- prelude kernels ----------------
__global__ void zero_deg_kernel(int* a, int* b, int n) {
    int i = blockIdx.x * blockDim.x + threadIdx.x;
    if (i < n) { a[i] = 0; b[i] = 0; }
}

__global__ void deg_kernel(const int* __restrict__ ei, int E, int* dgF, int* dgR) {
    int e = blockIdx.x * blockDim.x + threadIdx.x;
    if (e < E) {
        atomicAdd(dgF + ei[E + e], 1);
        atomicAdd(dgR + ei[e],     1);
    }
}

__global__ void prep_kernel(const int* dgF, const int* dgR, float* dF, float* dR, int n,
                            const float* __restrict__ W1, const float* __restrict__ W2,
                            float* W1T, float* W2T) {
    int i = blockIdx.x * blockDim.x + threadIdx.x;
    if (i < n) {
        dF[i] = rsqrtf((float)dgF[i] + 1.f);
        dR[i] = rsqrtf((float)dgR[i] + 1.f);
    }
    if (i < D * D) {
        int j = i >> 7, k = i & 127;
        W1T[k * D + j] = W1[i];
        W2T[k * D + j] = W2[i];
    }
}

__global__ void scan_bsum_kernel(const int* __restrict__ degF, const int* __restrict__ degR,
                                 int* bsF, int* bsR, int n) {
    __shared__ int sf[8], sr[8];
    int b = blockIdx.x, t = threadIdx.x;
    int aF = 0, aR = 0;
    int base = b * 1024;
    for (int j = t; j < 1024; j += 256) {
        int i = base + j;
        if (i < n) { aF += degF[i]; aR += degR[i]; }
    }
#pragma unroll
    for (int o = 16; o; o >>= 1) {
        aF += __shfl_down_sync(0xffffffffu, aF, o);
        aR += __shfl_down_sync(0xffffffffu, aR, o);
    }
    if ((t & 31) == 0) { sf[t >> 5] = aF; sr[t >> 5] = aR; }
    __syncthreads();
    if (t < 8) {
        aF = sf[t]; aR = sr[t];
#pragma unroll
        for (int o = 4; o; o >>= 1) {
            aF += __shfl_down_sync(0xffu, aF, o);
            aR += __shfl_down_sync(0xffu, aR, o);
        }
        if (t == 0) { bsF[b] = aF; bsR[b] = aR; }
    }
}

__global__ void scan_write_kernel(const int* __restrict__ degF, const int* __restrict__ degR,
                                  const int* __restrict__ bsF, const int* __restrict__ bsR,
                                  int* offF, int* offR, int* curF, int* curR, int n) {
    __shared__ int sF[32], sR[32];
    __shared__ int baseF, baseR;
    int b = blockIdx.x, t = threadIdx.x, lane = t & 31, w = t >> 5;
    if (t == 0) {
        int bf = 0, br = 0;
        for (int j = 0; j < b; j++) { bf += bsF[j]; br += bsR[j]; }
        baseF = bf; baseR = br;
    }
    int i = b * 1024 + t;
    int vF = (i < n) ? degF[i] : 0;
    int vR = (i < n) ? degR[i] : 0;
    int iF = vF, iR = vR;
#pragma unroll
    for (int o = 1; o < 32; o <<= 1) {
        int a = __shfl_up_sync(0xffffffffu, iF, o);
        int c = __shfl_up_sync(0xffffffffu, iR, o);
        if (lane >= o) { iF += a; iR += c; }
    }
    if (lane == 31) { sF[w] = iF; sR[w] = iR; }
    __syncthreads();
    if (w == 0) {
        int aF = sF[lane], aR = sR[lane];
#pragma unroll
        for (int o = 1; o < 32; o <<= 1) {
            int a = __shfl_up_sync(0xffffffffu, aF, o);
            int c = __shfl_up_sync(0xffffffffu, aR, o);
            if (lane >= o) { aF += a; aR += c; }
        }
        sF[lane] = aF; sR[lane] = aR;
    }
    __syncthreads();
    int pF = (w > 0) ? sF[w - 1] : 0;
    int pR = (w > 0) ? sR[w - 1] : 0;
    if (i < n) {
        int exF = baseF + pF + iF - vF;
        int exR = baseR + pR + iR - vR;
        offF[i] = exF; offR[i] = exR;
        curF[i] = exF; curR[i] = exR;
    }
}

__global__ void fill_csr_kernel(const int* __restrict__ ei, int E,
                                const float* __restrict__ dF, const float* __restrict__ dR,
                                int* curF, int* curR, int2* csrF, int2* csrR) {
    int e = blockIdx.x * blockDim.x + threadIdx.x;
    if (e >= E) return;
    int s = ei[e];
    int d = ei[E + e];
    float cf = dF[s] * dF[d];
    float cr = dR[s] * dR[d];
    int pF = atomicAdd(curF + d, 1);
    csrF[pF] = make_int2(s, __float_as_int(cf));
    int pR = atomicAdd(curR + s, 1);
    csrR[pR] = make_int2(d, __float_as_int(cr));
}

// ---------------- chunk fill: fp32 -> tf32 hi/lo, XOR-swizzled smem -------------
// chunk = 128 rows x 32 k floats. idx(row,k) = row*32 + (k ^ ((row&7)*4)).
__device__ __forceinline__ void fill_chunk(float* sh, float* sl,
                                           const float* __restrict__ G,
                                           int row0, int nvalid, int kc0, int tid) {
    for (int q = tid; q < 1024; q += 256) {
        int row = q >> 3;
        int k = (q & 7) * 4;
        float4 v = make_float4(0.f, 0.f, 0.f, 0.f);
        if (row < nvalid)
            v = *(const float4*)(G + (size_t)(row0 + row) * D + kc0 + k);
        float4 hi, lo;
        hi.x = tf32_rna(v.x); lo.x = tf32_rna(v.x - hi.x);
        hi.y = tf32_rna(v.y); lo.y = tf32_rna(v.y - hi.y);
        hi.z = tf32_rna(v.z); lo.z = tf32_rna(v.z - hi.z);
        hi.w = tf32_rna(v.w); lo.w = tf32_rna(v.w - hi.w);
        int s = row * 32 + (k ^ ((row & 7) * 4));
        *(float4*)(sh + s) = hi;
        *(float4*)(sl + s) = lo;
    }
}

// ---------------- tf32x3 mma.sync GEMM ----------------
// GATE=0: C[M,128] = Aa[M,128] @ Ba^T     (Ba row-major [N,K])
// GATE=1: C = sig(Aa@Ba^T + Ab@Bb^T + bias)*Aa + (1-sig)*Ab
template<int GATE>
__global__ void __launch_bounds__(256)
mma_gemm_kernel(const float* __restrict__ Aa, const float* __restrict__ Ab,
                const float* __restrict__ Ba, const float* __restrict__ Bb,
                const float* __restrict__ bias, float* __restrict__ C, int M) {
    extern __shared__ float sm[];
    float* AH = sm;
    float* AL = sm + 4096;
    float* BH = sm + 8192;
    float* BL = sm + 12288;

    const int tid  = threadIdx.x;
    const int wid  = tid >> 5;
    const int lane = tid & 31;
    const int g    = lane >> 2;       // group id 0..7
    const int c    = lane & 3;        // thread in group
    const int wm   = wid & 3;         // warp row (32 rows each)
    const int wn   = wid >> 2;        // warp col (64 cols each)
    const int m0   = blockIdx.x * 128;
    const int nvalid = min(128, M - m0);
    const int X    = g * 4;           // xor swizzle mask (row&7 == g for all frags)

    const int arow = (wm * 32 + g) * 32;     // A row base (float idx)
    const int nrow = (wn * 64 + g) * 32;     // B row base

    float acc[2][8][4];
#pragma unroll
    for (int mt = 0; mt < 2; mt++)
#pragma unroll
        for (int nt = 0; nt < 8; nt++)
#pragma unroll
            for (int r = 0; r < 4; r++) acc[mt][nt][r] = 0.f;

    const int NCH = GATE ? 8 : 4;
    for (int ch = 0; ch < NCH; ch++) {
        const float* A = (GATE && ch >= 4) ? Ab : Aa;
        const float* B = (GATE && ch >= 4) ? Bb : Ba;
        const int kc0 = (ch & 3) * 32;
        __syncthreads();
        fill_chunk(AH, AL, A, m0, nvalid, kc0, tid);
        fill_chunk(BH, BL, B, 0, 128, kc0, tid);
        __syncthreads();
#pragma unroll
        for (int ks = 0; ks < 4; ks++) {
            uint32_t aH[2][4], aL[2][4];
#pragma unroll
            for (int mt = 0; mt < 2; mt++) {
#pragma unroll
                for (int rh = 0; rh < 2; rh++) {
#pragma unroll
                    for (int chf = 0; chf < 2; chf++) {
                        int idx = arow + mt * 512 + rh * 256 +
                                  ((ks * 8 + c + chf * 4) ^ X);
                        aH[mt][rh + chf * 2] = __float_as_uint(AH[idx]);
                        aL[mt][rh + chf * 2] = __float_as_uint(AL[idx]);
                    }
                }
            }
#pragma unroll
            for (int nt = 0; nt < 8; nt++) {
                int i0 = nrow + nt * 256 + ((ks * 8 + c) ^ X);
                int i1 = nrow + nt * 256 + ((ks * 8 + c + 4) ^ X);
                uint32_t bh0 = __float_as_uint(BH[i0]);
                uint32_t bh1 = __float_as_uint(BH[i1]);
                uint32_t bl0 = __float_as_uint(BL[i0]);
                uint32_t bl1 = __float_as_uint(BL[i1]);
#pragma unroll
                for (int mt = 0; mt < 2; mt++) {
                    mma8(acc[mt][nt], aH[mt][0], aH[mt][1], aH[mt][2], aH[mt][3], bh0, bh1);
                    mma8(acc[mt][nt], aL[mt][0], aL[mt][1], aL[mt][2], aL[mt][3], bh0, bh1);
                    mma8(acc[mt][nt], aH[mt][0], aH[mt][1], aH[mt][2], aH[mt][3], bl0, bl1);
                }
            }
        }
    }

    // epilogue: acc[mt][nt][r]: row = m0 + wm*32 + mt*16 + g + (r>=2)*8,
    //           col = wn*64 + nt*8 + c*2 + (r&1)
#pragma unroll
    for (int mt = 0; mt < 2; mt++) {
#pragma unroll
        for (int rh = 0; rh < 2; rh++) {
            int row = m0 + wm * 32 + mt * 16 + g + rh * 8;
            if (row >= M) continue;
#pragma unroll
            for (int nt = 0; nt < 8; nt++) {
                int col = wn * 64 + nt * 8 + c * 2;
                float v0 = acc[mt][nt][rh * 2 + 0];
                float v1 = acc[mt][nt][rh * 2 + 1];
                if (!GATE) {
                    *(float2*)(C + (size_t)row * D + col) = make_float2(v0, v1);
                } else {
                    float2 bb = *(const float2*)(bias + col);
                    float2 o1 = *(const float2*)(Aa + (size_t)row * D + col);
                    float2 o2 = *(const float2*)(Ab + (size_t)row * D + col);
                    float g0 = 1.f / (1.f + __expf(-(v0 + bb.x)));
                    float g1 = 1.f / (1.f + __expf(-(v1 + bb.y)));
                    float2 o;
                    o.x = g0 * o1.x + (1.f - g0) * o2.x;
                    o.y = g1 * o1.y + (1.f - g1) * o2.y;
                    *(float2*)(C + (size_t)row * D + col) = o;
                }
            }
        }
    }
}

// ---------------- gather: one warp per node, both directions, fused epilogue ------
__global__ void gather_kernel(const float* __restrict__ H,
                              const int2* __restrict__ csrF, const int2* __restrict__ csrR,
                              const int* __restrict__ offF, const int* __restrict__ offR,
                              const int* __restrict__ degF, const int* __restrict__ degR,
                              const float* __restrict__ dF, const float* __restrict__ dR,
                              const float* __restrict__ bias,
                              float* __restrict__ A1, float* __restrict__ A2, int N) {
    int w = (blockIdx.x * blockDim.x + threadIdx.x) >> 5;
    int lane = threadIdx.x & 31;
    if (w >= N) return;

    float4 acc1 = make_float4(0.f, 0.f, 0.f, 0.f);
    float4 acc2 = make_float4(0.f, 0.f, 0.f, 0.f);

    int oF = offF[w], nF = degF[w];
    for (int b = 0; b < nF; b += 32) {
        int m = min(32, nF - b);
        int2 ent = (lane < m) ? csrF[oF + b + lane] : make_int2(0, 0);
        for (int j = 0; j < m; j++) {
            int   idx = __shfl_sync(0xffffffffu, ent.x, j);
            float cc  = __int_as_float(__shfl_sync(0xffffffffu, ent.y, j));
            float4 hv = ((const float4*)H)[idx * 32 + lane];
            acc1.x = fmaf(hv.x, cc, acc1.x);
            acc1.y = fmaf(hv.y, cc, acc1.y);
            acc1.z = fmaf(hv.z, cc, acc1.z);
            acc1.w = fmaf(hv.w, cc, acc1.w);
        }
    }
    int oR = offR[w], nR = degR[w];
    for (int b = 0; b < nR; b += 32) {
        int m = min(32, nR - b);
        int2 ent = (lane < m) ? csrR[oR + b + lane] : make_int2(0, 0);
        for (int j = 0; j < m; j++) {
            int   idx = __shfl_sync(0xffffffffu, ent.x, j);
            float cc  = __int_as_float(__shfl_sync(0xffffffffu, ent.y, j));
            float4 hv = ((const float4*)H)[idx * 32 + lane];
            acc2.x = fmaf(hv.x, cc, acc2.x);
            acc2.y = fmaf(hv.y, cc, acc2.y);
            acc2.z = fmaf(hv.z, cc, acc2.z);
            acc2.w = fmaf(hv.w, cc, acc2.w);
        }
    }
    float4 hn = ((const float4*)H)[w * 32 + lane];
    float4 bb = ((const float4*)bias)[lane];
    float f2 = dF[w]; f2 *= f2;
    float r2 = dR[w]; r2 *= r2;
    float4 a1, a2;
    a1.x = fmaxf(fmaf(hn.x, f2, acc1.x) + bb.x, 0.f);
    a1.y = fmaxf(fmaf(hn.y, f2, acc1.y) + bb.y, 0.f);
    a1.z = fmaxf(fmaf(hn.z, f2, acc1.z) + bb.z, 0.f);
    a1.w = fmaxf(fmaf(hn.w, f2, acc1.w) + bb.w, 0.f);
    a2.x = fmaxf(fmaf(hn.x, r2, acc2.x) + bb.x, 0.f);
    a2.y = fmaxf(fmaf(hn.y, r2, acc2.y) + bb.y, 0.f);
    a2.z = fmaxf(fmaf(hn.z, r2, acc2.z) + bb.z, 0.f);
    a2.w = fmaxf(fmaf(hn.w, r2, acc2.w) + bb.w, 0.f);
    ((float4*)A1)[w * 32 + lane] = a1;
    ((float4*)A2)[w * 32 + lane] = a2;
}

// ---------------- driver ----------------
extern "C" void kernel_launch(void* const* d_in, const int* in_sizes, int n_in,
                              void* d_out, int out_size) {
    const float* x   = (const float*)d_in[0];
    const int*   ei  = (const int*)  d_in[1];
    const float* W1  = (const float*)d_in[2];
    const float* bc1 = (const float*)d_in[3];
    const float* W2  = (const float*)d_in[4];
    const float* bc2 = (const float*)d_in[5];
    const float* w11 = (const float*)d_in[6];
    const float* w12 = (const float*)d_in[7];
    const float* b1  = (const float*)d_in[8];
    const float* w21 = (const float*)d_in[9];
    const float* w22 = (const float*)d_in[10];
    const float* b2  = (const float*)d_in[11];

    const int N = in_sizes[0] / D;
    const int E = in_sizes[1] / 2;

    float *H, *A1, *A2, *HM, *dF, *dR, *W1T, *W2T;
    int *degF, *degR, *offF, *offR, *curF, *curR, *bsF, *bsR;
    int2 *csrF, *csrR;
    cudaGetSymbolAddress((void**)&H,    g_H);
    cudaGetSymbolAddress((void**)&A1,   g_A1);
    cudaGetSymbolAddress((void**)&A2,   g_A2);
    cudaGetSymbolAddress((void**)&HM,   g_HM);
    cudaGetSymbolAddress((void**)&degF, g_degF);
    cudaGetSymbolAddress((void**)&degR, g_degR);
    cudaGetSymbolAddress((void**)&offF, g_offF);
    cudaGetSymbolAddress((void**)&offR, g_offR);
    cudaGetSymbolAddress((void**)&curF, g_curF);
    cudaGetSymbolAddress((void**)&curR, g_curR);
    cudaGetSymbolAddress((void**)&dF,   g_dF);
    cudaGetSymbolAddress((void**)&dR,   g_dR);
    cudaGetSymbolAddress((void**)&csrF, g_csrF);
    cudaGetSymbolAddress((void**)&csrR, g_csrR);
    cudaGetSymbolAddress((void**)&W1T,  g_W1T);
    cudaGetSymbolAddress((void**)&W2T,  g_W2T);
    cudaGetSymbolAddress((void**)&bsF,  g_bsF);
    cudaGetSymbolAddress((void**)&bsR,  g_bsR);

    const int SMEM_BYTES = 16384 * 4;   // 64 KB
    cudaFuncSetAttribute(mma_gemm_kernel<0>, cudaFuncAttributeMaxDynamicSharedMemorySize, SMEM_BYTES);
    cudaFuncSetAttribute(mma_gemm_kernel<1>, cudaFuncAttributeMaxDynamicSharedMemorySize, SMEM_BYTES);

    const int TB = 256;
    const int gN    = (N + TB - 1) / TB;
    const int gE    = (E + TB - 1) / TB;
    const int gGath = (N * 32 + TB - 1) / TB;
    const int gMma  = (N + 127) / 128;
    const int nbs   = (N + 1023) / 1024;

    // prelude (5 launches)
    zero_deg_kernel<<<gN, TB>>>(degF, degR, N);
    deg_kernel<<<gE, TB>>>(ei, E, degF, degR);
    prep_kernel<<<gN, TB>>>(degF, degR, dF, dR, N, W1, W2, W1T, W2T);
    scan_bsum_kernel<<<nbs, TB>>>(degF, degR, bsF, bsR, N);
    scan_write_kernel<<<nbs, 1024>>>(degF, degR, bsF, bsR, offF, offR, curF, curR, N);

    // ================= layer 1 =================
    mma_gemm_kernel<0><<<gMma, TB, SMEM_BYTES>>>(x, nullptr, W1T, nullptr,
                                                 nullptr, H, N);                  // #6 profiled
    fill_csr_kernel<<<gE, TB>>>(ei, E, dF, dR, curF, curR, csrF, csrR);
    gather_kernel<<<gGath, TB>>>(H, csrF, csrR, offF, offR, degF, degR,
                                 dF, dR, bc1, A1, A2, N);
    mma_gemm_kernel<1><<<gMma, TB, SMEM_BYTES>>>(A1, A2, w11, w12, b1, HM, N);

    // ================= layer 2 =================
    mma_gemm_kernel<0><<<gMma, TB, SMEM_BYTES>>>(HM, nullptr, W2T, nullptr,
                                                 nullptr, H, N);
    gather_kernel<<<gGath, TB>>>(H, csrF, csrR, offF, offR, degF, degR,
                                 dF, dR, bc2, A1, A2, N);
    mma_gemm_kernel<1><<<gMma, TB, SMEM_BYTES>>>(A1, A2, w21, w22, b2,
                                                 (float*)d_out, N);
}

// round 5
// speedup vs baseline: 1.2203x; 1.2203x over previous
#include <cuda_runtime.h>
#include <math.h>
#include <stdint.h>

#define D 128
#define MAXN 50000
#define MAXE 800000
#define NBS ((MAXN + 1023) / 1024)

// ---------------- scratch ----------------
__device__ float g_H [MAXN * D];
__device__ float g_A1[MAXN * D];
__device__ float g_A2[MAXN * D];
__device__ float g_HM[MAXN * D];
__device__ int   g_degF[MAXN];
__device__ int   g_degR[MAXN];
__device__ int   g_offF[MAXN];
__device__ int   g_offR[MAXN];
__device__ int   g_curF[MAXN];
__device__ int   g_curR[MAXN];
__device__ float g_dF[MAXN];
__device__ float g_dR[MAXN];
__device__ int2  g_csrF[MAXE];
__device__ int2  g_csrR[MAXE];
__device__ float g_T11[D * D];
__device__ float g_T12[D * D];
__device__ float g_T21[D * D];
__device__ float g_T22[D * D];
__device__ int   g_bsF[NBS + 1];
__device__ int   g_bsR[NBS + 1];

// ---------------- prelude kernels ----------------
__global__ void zero_deg_kernel(int* a, int* b, int n) {
    int i = blockIdx.x * blockDim.x + threadIdx.x;
    if (i < n) { a[i] = 0; b[i] = 0; }
}

__global__ void deg_kernel(const int* __restrict__ ei, int E, int* dgF, int* dgR) {
    int e = blockIdx.x * blockDim.x + threadIdx.x;
    if (e < E) {
        atomicAdd(dgF + ei[E + e], 1);
        atomicAdd(dgR + ei[e],     1);
    }
}

// dinv + transpose all 4 gate weights into [K,N] form
__global__ void prep_kernel(const int* dgF, const int* dgR, float* dF, float* dR, int n,
                            const float* __restrict__ w11, const float* __restrict__ w12,
                            const float* __restrict__ w21, const float* __restrict__ w22,
                            float* T11, float* T12, float* T21, float* T22) {
    int i = blockIdx.x * blockDim.x + threadIdx.x;
    if (i < n) {
        dF[i] = rsqrtf((float)dgF[i] + 1.f);
        dR[i] = rsqrtf((float)dgR[i] + 1.f);
    }
    if (i < D * D) {
        int j = i >> 7, k = i & 127;
        T11[k * D + j] = w11[i];
        T12[k * D + j] = w12[i];
        T21[k * D + j] = w21[i];
        T22[k * D + j] = w22[i];
    }
}

__global__ void scan_bsum_kernel(const int* __restrict__ degF, const int* __restrict__ degR,
                                 int* bsF, int* bsR, int n) {
    __shared__ int sf[8], sr[8];
    int b = blockIdx.x, t = threadIdx.x;
    int aF = 0, aR = 0;
    int base = b * 1024;
    for (int j = t; j < 1024; j += 256) {
        int i = base + j;
        if (i < n) { aF += degF[i]; aR += degR[i]; }
    }
#pragma unroll
    for (int o = 16; o; o >>= 1) {
        aF += __shfl_down_sync(0xffffffffu, aF, o);
        aR += __shfl_down_sync(0xffffffffu, aR, o);
    }
    if ((t & 31) == 0) { sf[t >> 5] = aF; sr[t >> 5] = aR; }
    __syncthreads();
    if (t < 8) {
        aF = sf[t]; aR = sr[t];
#pragma unroll
        for (int o = 4; o; o >>= 1) {
            aF += __shfl_down_sync(0xffu, aF, o);
            aR += __shfl_down_sync(0xffu, aR, o);
        }
        if (t == 0) { bsF[b] = aF; bsR[b] = aR; }
    }
}

__global__ void scan_write_kernel(const int* __restrict__ degF, const int* __restrict__ degR,
                                  const int* __restrict__ bsF, const int* __restrict__ bsR,
                                  int* offF, int* offR, int* curF, int* curR, int n) {
    __shared__ int sF[32], sR[32];
    __shared__ int baseF, baseR;
    int b = blockIdx.x, t = threadIdx.x, lane = t & 31, w = t >> 5;
    if (t == 0) {
        int bf = 0, br = 0;
        for (int j = 0; j < b; j++) { bf += bsF[j]; br += bsR[j]; }
        baseF = bf; baseR = br;
    }
    int i = b * 1024 + t;
    int vF = (i < n) ? degF[i] : 0;
    int vR = (i < n) ? degR[i] : 0;
    int iF = vF, iR = vR;
#pragma unroll
    for (int o = 1; o < 32; o <<= 1) {
        int a = __shfl_up_sync(0xffffffffu, iF, o);
        int c = __shfl_up_sync(0xffffffffu, iR, o);
        if (lane >= o) { iF += a; iR += c; }
    }
    if (lane == 31) { sF[w] = iF; sR[w] = iR; }
    __syncthreads();
    if (w == 0) {
        int aF = sF[lane], aR = sR[lane];
#pragma unroll
        for (int o = 1; o < 32; o <<= 1) {
            int a = __shfl_up_sync(0xffffffffu, aF, o);
            int c = __shfl_up_sync(0xffffffffu, aR, o);
            if (lane >= o) { aF += a; aR += c; }
        }
        sF[lane] = aF; sR[lane] = aR;
    }
    __syncthreads();
    int pF = (w > 0) ? sF[w - 1] : 0;
    int pR = (w > 0) ? sR[w - 1] : 0;
    if (i < n) {
        int exF = baseF + pF + iF - vF;
        int exR = baseR + pR + iR - vR;
        offF[i] = exF; offR[i] = exR;
        curF[i] = exF; curR[i] = exR;
    }
}

__global__ void fill_csr_kernel(const int* __restrict__ ei, int E,
                                const float* __restrict__ dF, const float* __restrict__ dR,
                                int* curF, int* curR, int2* csrF, int2* csrR) {
    int e = blockIdx.x * blockDim.x + threadIdx.x;
    if (e >= E) return;
    int s = ei[e];
    int d = ei[E + e];
    float cf = dF[s] * dF[d];
    float cr = dR[s] * dR[d];
    int pF = atomicAdd(curF + d, 1);
    csrF[pF] = make_int2(s, __float_as_int(cf));
    int pR = atomicAdd(curR + s, 1);
    csrR[pR] = make_int2(d, __float_as_int(cr));
}

// ---------------- GEMM: 128x128 tile, k-vectorized smem reads ----------------
// GATE=0: C[M,128] = Aa @ Ba          (Ba is [K,N] row-major)
// GATE=1: C = sig(Aa@Ba + Ab@Bb + bias)*Aa + (1-sig)*Ab
// 256 threads = 8 warps; warp ty owns rows {ty + 8*i}, thread col group tx (4 cols).
template<int GATE>
__global__ void __launch_bounds__(256)
gemm_kernel(const float* __restrict__ Aa, const float* __restrict__ Ab,
            const float* __restrict__ Ba, const float* __restrict__ Bb,
            const float* __restrict__ bias, float* __restrict__ C, int M) {
    __shared__ float4 Ws[32][32];     // [k][col4]  16 KB
    __shared__ float4 As4[128][8];    // [row][k4]  16 KB

    const int tid = threadIdx.x;
    const int tx  = tid & 31;
    const int ty  = tid >> 5;
    const int m0  = blockIdx.x * 128;

    float4 acc[16];
#pragma unroll
    for (int i = 0; i < 16; i++) acc[i] = make_float4(0.f, 0.f, 0.f, 0.f);

    const int NCH = GATE ? 8 : 4;
    for (int ch = 0; ch < NCH; ch++) {
        const float* A = (GATE && ch >= 4) ? Ab : Aa;
        const float* B = (GATE && ch >= 4) ? Bb : Ba;
        const int kc0 = (ch & 3) * 32;
        __syncthreads();
        // Ws: 1024 float4, 4 per thread (coalesced)
#pragma unroll
        for (int i = 0; i < 4; i++) {
            int f = i * 256 + tid;
            int k = f >> 5, j4 = f & 31;
            Ws[k][j4] = ((const float4*)B)[(kc0 + k) * 32 + j4];
        }
        // As4: 1024 float4 (128 rows x 8 k4), 4 per thread
#pragma unroll
        for (int i = 0; i < 4; i++) {
            int f = i * 256 + tid;
            int r = f >> 3, k4 = f & 7;
            int gm = m0 + r;
            As4[r][k4] = (gm < M) ? ((const float4*)A)[gm * 32 + (kc0 >> 2) + k4]
                                  : make_float4(0.f, 0.f, 0.f, 0.f);
        }
        __syncthreads();
#pragma unroll
        for (int k4 = 0; k4 < 8; k4++) {
            float4 b0 = Ws[k4 * 4 + 0][tx];
            float4 b1 = Ws[k4 * 4 + 1][tx];
            float4 b2 = Ws[k4 * 4 + 2][tx];
            float4 b3 = Ws[k4 * 4 + 3][tx];
#pragma unroll
            for (int i = 0; i < 16; i++) {
                float4 a = As4[ty + 8 * i][k4];   // warp-uniform -> broadcast
                acc[i].x = fmaf(a.x, b0.x, acc[i].x);
                acc[i].y = fmaf(a.x, b0.y, acc[i].y);
                acc[i].z = fmaf(a.x, b0.z, acc[i].z);
                acc[i].w = fmaf(a.x, b0.w, acc[i].w);
                acc[i].x = fmaf(a.y, b1.x, acc[i].x);
                acc[i].y = fmaf(a.y, b1.y, acc[i].y);
                acc[i].z = fmaf(a.y, b1.z, acc[i].z);
                acc[i].w = fmaf(a.y, b1.w, acc[i].w);
                acc[i].x = fmaf(a.z, b2.x, acc[i].x);
                acc[i].y = fmaf(a.z, b2.y, acc[i].y);
                acc[i].z = fmaf(a.z, b2.z, acc[i].z);
                acc[i].w = fmaf(a.z, b2.w, acc[i].w);
                acc[i].x = fmaf(a.w, b3.x, acc[i].x);
                acc[i].y = fmaf(a.w, b3.y, acc[i].y);
                acc[i].z = fmaf(a.w, b3.z, acc[i].z);
                acc[i].w = fmaf(a.w, b3.w, acc[i].w);
            }
        }
    }
    // epilogue
#pragma unroll
    for (int i = 0; i < 16; i++) {
        int row = m0 + ty + 8 * i;
        if (row >= M) continue;
        if (!GATE) {
            ((float4*)C)[row * 32 + tx] = acc[i];
        } else {
            float4 bb = ((const float4*)bias)[tx];
            float4 o1 = ((const float4*)Aa)[row * 32 + tx];
            float4 o2 = ((const float4*)Ab)[row * 32 + tx];
            float gx = 1.f / (1.f + __expf(-(acc[i].x + bb.x)));
            float gy = 1.f / (1.f + __expf(-(acc[i].y + bb.y)));
            float gz = 1.f / (1.f + __expf(-(acc[i].z + bb.z)));
            float gw = 1.f / (1.f + __expf(-(acc[i].w + bb.w)));
            float4 o;
            o.x = gx * o1.x + (1.f - gx) * o2.x;
            o.y = gy * o1.y + (1.f - gy) * o2.y;
            o.z = gz * o1.z + (1.f - gz) * o2.z;
            o.w = gw * o1.w + (1.f - gw) * o2.w;
            ((float4*)C)[row * 32 + tx] = o;
        }
    }
}

// ---------------- gather: one warp per node, both directions, fused epilogue ------
__global__ void gather_kernel(const float* __restrict__ H,
                              const int2* __restrict__ csrF, const int2* __restrict__ csrR,
                              const int* __restrict__ offF, const int* __restrict__ offR,
                              const int* __restrict__ degF, const int* __restrict__ degR,
                              const float* __restrict__ dF, const float* __restrict__ dR,
                              const float* __restrict__ bias,
                              float* __restrict__ A1, float* __restrict__ A2, int N) {
    int w = (blockIdx.x * blockDim.x + threadIdx.x) >> 5;
    int lane = threadIdx.x & 31;
    if (w >= N) return;

    float4 acc1 = make_float4(0.f, 0.f, 0.f, 0.f);
    float4 acc2 = make_float4(0.f, 0.f, 0.f, 0.f);

    int oF = offF[w], nF = degF[w];
    for (int b = 0; b < nF; b += 32) {
        int m = min(32, nF - b);
        int2 ent = (lane < m) ? csrF[oF + b + lane] : make_int2(0, 0);
        for (int j = 0; j < m; j++) {
            int   idx = __shfl_sync(0xffffffffu, ent.x, j);
            float cc  = __int_as_float(__shfl_sync(0xffffffffu, ent.y, j));
            float4 hv = ((const float4*)H)[idx * 32 + lane];
            acc1.x = fmaf(hv.x, cc, acc1.x);
            acc1.y = fmaf(hv.y, cc, acc1.y);
            acc1.z = fmaf(hv.z, cc, acc1.z);
            acc1.w = fmaf(hv.w, cc, acc1.w);
        }
    }
    int oR = offR[w], nR = degR[w];
    for (int b = 0; b < nR; b += 32) {
        int m = min(32, nR - b);
        int2 ent = (lane < m) ? csrR[oR + b + lane] : make_int2(0, 0);
        for (int j = 0; j < m; j++) {
            int   idx = __shfl_sync(0xffffffffu, ent.x, j);
            float cc  = __int_as_float(__shfl_sync(0xffffffffu, ent.y, j));
            float4 hv = ((const float4*)H)[idx * 32 + lane];
            acc2.x = fmaf(hv.x, cc, acc2.x);
            acc2.y = fmaf(hv.y, cc, acc2.y);
            acc2.z = fmaf(hv.z, cc, acc2.z);
            acc2.w = fmaf(hv.w, cc, acc2.w);
        }
    }
    float4 hn = ((const float4*)H)[w * 32 + lane];
    float4 bb = ((const float4*)bias)[lane];
    float f2 = dF[w]; f2 *= f2;
    float r2 = dR[w]; r2 *= r2;
    float4 a1, a2;
    a1.x = fmaxf(fmaf(hn.x, f2, acc1.x) + bb.x, 0.f);
    a1.y = fmaxf(fmaf(hn.y, f2, acc1.y) + bb.y, 0.f);
    a1.z = fmaxf(fmaf(hn.z, f2, acc1.z) + bb.z, 0.f);
    a1.w = fmaxf(fmaf(hn.w, f2, acc1.w) + bb.w, 0.f);
    a2.x = fmaxf(fmaf(hn.x, r2, acc2.x) + bb.x, 0.f);
    a2.y = fmaxf(fmaf(hn.y, r2, acc2.y) + bb.y, 0.f);
    a2.z = fmaxf(fmaf(hn.z, r2, acc2.z) + bb.z, 0.f);
    a2.w = fmaxf(fmaf(hn.w, r2, acc2.w) + bb.w, 0.f);
    ((float4*)A1)[w * 32 + lane] = a1;
    ((float4*)A2)[w * 32 + lane] = a2;
}

// ---------------- driver ----------------
extern "C" void kernel_launch(void* const* d_in, const int* in_sizes, int n_in,
                              void* d_out, int out_size) {
    const float* x   = (const float*)d_in[0];
    const int*   ei  = (const int*)  d_in[1];
    const float* W1  = (const float*)d_in[2];
    const float* bc1 = (const float*)d_in[3];
    const float* W2  = (const float*)d_in[4];
    const float* bc2 = (const float*)d_in[5];
    const float* w11 = (const float*)d_in[6];
    const float* w12 = (const float*)d_in[7];
    const float* b1  = (const float*)d_in[8];
    const float* w21 = (const float*)d_in[9];
    const float* w22 = (const float*)d_in[10];
    const float* b2  = (const float*)d_in[11];

    const int N = in_sizes[0] / D;
    const int E = in_sizes[1] / 2;

    float *H, *A1, *A2, *HM, *dF, *dR, *T11, *T12, *T21, *T22;
    int *degF, *degR, *offF, *offR, *curF, *curR, *bsF, *bsR;
    int2 *csrF, *csrR;
    cudaGetSymbolAddress((void**)&H,    g_H);
    cudaGetSymbolAddress((void**)&A1,   g_A1);
    cudaGetSymbolAddress((void**)&A2,   g_A2);
    cudaGetSymbolAddress((void**)&HM,   g_HM);
    cudaGetSymbolAddress((void**)&degF, g_degF);
    cudaGetSymbolAddress((void**)&degR, g_degR);
    cudaGetSymbolAddress((void**)&offF, g_offF);
    cudaGetSymbolAddress((void**)&offR, g_offR);
    cudaGetSymbolAddress((void**)&curF, g_curF);
    cudaGetSymbolAddress((void**)&curR, g_curR);
    cudaGetSymbolAddress((void**)&dF,   g_dF);
    cudaGetSymbolAddress((void**)&dR,   g_dR);
    cudaGetSymbolAddress((void**)&csrF, g_csrF);
    cudaGetSymbolAddress((void**)&csrR, g_csrR);
    cudaGetSymbolAddress((void**)&T11,  g_T11);
    cudaGetSymbolAddress((void**)&T12,  g_T12);
    cudaGetSymbolAddress((void**)&T21,  g_T21);
    cudaGetSymbolAddress((void**)&T22,  g_T22);
    cudaGetSymbolAddress((void**)&bsF,  g_bsF);
    cudaGetSymbolAddress((void**)&bsR,  g_bsR);

    const int TB = 256;
    const int gN    = (N + TB - 1) / TB;
    const int gE    = (E + TB - 1) / TB;
    const int gGath = (N * 32 + TB - 1) / TB;
    const int gMma  = (N + 127) / 128;
    const int nbs   = (N + 1023) / 1024;

    zero_deg_kernel<<<gN, TB>>>(degF, degR, N);                                   // 1
    deg_kernel<<<gE, TB>>>(ei, E, degF, degR);                                    // 2
    prep_kernel<<<gN, TB>>>(degF, degR, dF, dR, N,
                            w11, w12, w21, w22, T11, T12, T21, T22);              // 3
    gemm_kernel<0><<<gMma, TB>>>(x, nullptr, W1, nullptr, nullptr, H, N);         // 4 PROFILED
    scan_bsum_kernel<<<nbs, TB>>>(degF, degR, bsF, bsR, N);                       // 5
    scan_write_kernel<<<nbs, 1024>>>(degF, degR, bsF, bsR, offF, offR, curF, curR, N); // 6
    fill_csr_kernel<<<gE, TB>>>(ei, E, dF, dR, curF, curR, csrF, csrR);           // 7

    // ================= layer 1 =================
    gather_kernel<<<gGath, TB>>>(H, csrF, csrR, offF, offR, degF, degR,
                                 dF, dR, bc1, A1, A2, N);
    gemm_kernel<1><<<gMma, TB>>>(A1, A2, T11, T12, b1, HM, N);

    // ================= layer 2 =================
    gemm_kernel<0><<<gMma, TB>>>(HM, nullptr, W2, nullptr, nullptr, H, N);
    gather_kernel<<<gGath, TB>>>(H, csrF, csrR, offF, offR, degF, degR,
                                 dF, dR, bc2, A1, A2, N);
    gemm_kernel<1><<<gMma, TB>>>(A1, A2, T21, T22, b2, (float*)d_out, N);
}